// round 1
// baseline (speedup 1.0000x reference)
#include <cuda_runtime.h>
#include <math.h>

#define BB 2
#define SS 2048
#define DD 768
#define HH 12
#define DH 64
#define MM (BB*SS)

// scratch (no allocations allowed — __device__ globals are the sanctioned path)
__device__ float g_q[MM*DD];
__device__ float g_k[MM*DD];
__device__ float g_v[MM*DD];
__device__ float g_ctx[MM*DD];

// ---------------------------------------------------------------------------
// SGEMM: C[M,N] = A[M,K] @ W[K,N] + bias[N]
// BM=BN=64, BK=16, 256 threads, 4x4 register tile per thread.
// ---------------------------------------------------------------------------
__global__ void gemm_bias_kernel(const float* __restrict__ A,
                                 const float* __restrict__ W,
                                 const float* __restrict__ bias,
                                 float* __restrict__ C,
                                 int Mdim, int Ndim, int Kdim)
{
    __shared__ float As[16][64];   // [k][m]
    __shared__ float Bs[16][64];   // [k][n]

    const int tid = threadIdx.x;
    const int ty  = tid >> 4;       // 0..15
    const int tx  = tid & 15;       // 0..15
    const int m0  = blockIdx.y * 64;
    const int n0  = blockIdx.x * 64;

    float acc[4][4] = {};

    for (int k0 = 0; k0 < Kdim; k0 += 16) {
        // A tile: each thread loads one float4 along K
        {
            const int am = tid >> 2;          // 0..63
            const int ak = (tid & 3) * 4;     // 0,4,8,12
            float4 av = *reinterpret_cast<const float4*>(
                &A[(long)(m0 + am) * Kdim + k0 + ak]);
            As[ak + 0][am] = av.x;
            As[ak + 1][am] = av.y;
            As[ak + 2][am] = av.z;
            As[ak + 3][am] = av.w;
        }
        // B tile: each thread loads one float4 along N
        {
            const int bk = tid >> 4;          // 0..15
            const int bn = (tid & 15) * 4;    // 0..60
            *reinterpret_cast<float4*>(&Bs[bk][bn]) =
                *reinterpret_cast<const float4*>(
                    &W[(long)(k0 + bk) * Ndim + n0 + bn]);
        }
        __syncthreads();

#pragma unroll
        for (int k = 0; k < 16; k++) {
            float4 av = *reinterpret_cast<float4*>(&As[k][ty * 4]);
            float4 bv = *reinterpret_cast<float4*>(&Bs[k][tx * 4]);
            float a4[4] = {av.x, av.y, av.z, av.w};
            float b4[4] = {bv.x, bv.y, bv.z, bv.w};
#pragma unroll
            for (int i = 0; i < 4; i++)
#pragma unroll
                for (int j = 0; j < 4; j++)
                    acc[i][j] += a4[i] * b4[j];
        }
        __syncthreads();
    }

    float4 bv = *reinterpret_cast<const float4*>(&bias[n0 + tx * 4]);
#pragma unroll
    for (int i = 0; i < 4; i++) {
        const int row = m0 + ty * 4 + i;
        float4 o;
        o.x = acc[i][0] + bv.x;
        o.y = acc[i][1] + bv.y;
        o.z = acc[i][2] + bv.z;
        o.w = acc[i][3] + bv.w;
        *reinterpret_cast<float4*>(&C[(long)row * Ndim + n0 + tx * 4]) = o;
    }
}

// ---------------------------------------------------------------------------
// Flash attention (fp32, no scaling): per block = one (b,h) and 64 queries.
// Loops over 32 key tiles of 64 with online softmax. O kept in registers.
// ---------------------------------------------------------------------------
#define SSTR 65   // +1 padding to break bank conflicts

extern __shared__ float sm_att[];

__global__ void attn_kernel()
{
    const int bh = blockIdx.y;
    const int b  = bh / HH;
    const int h  = bh % HH;
    const int q0 = blockIdx.x * 64;

    float* Qs   = sm_att;
    float* Ks   = Qs + 64 * SSTR;
    float* Vs   = Ks + 64 * SSTR;
    float* Ss   = Vs + 64 * SSTR;
    float* mrow = Ss + 64 * SSTR;
    float* lrow = mrow + 64;
    float* frow = lrow + 64;

    const int tid = threadIdx.x;
    const int r0  = (tid >> 4) * 4;   // query rows
    const int c0  = (tid & 15) * 4;   // key cols / dh cols

    // load Q tile
    for (int idx = tid; idx < 64 * 64; idx += 256) {
        const int r = idx >> 6, c = idx & 63;
        Qs[r * SSTR + c] = g_q[(long)(b * SS + q0 + r) * DD + h * DH + c];
    }
    if (tid < 64) { mrow[tid] = -INFINITY; lrow[tid] = 0.0f; }

    float o[4][4] = {};
    __syncthreads();

    for (int kt = 0; kt < SS / 64; kt++) {
        const int k0 = kt * 64;
        // load K and V tiles
        for (int idx = tid; idx < 64 * 64; idx += 256) {
            const int r = idx >> 6, c = idx & 63;
            const long g = (long)(b * SS + k0 + r) * DD + h * DH + c;
            Ks[r * SSTR + c] = g_k[g];
            Vs[r * SSTR + c] = g_v[g];
        }
        __syncthreads();

        // S = Q @ K^T   (64x64, 4x4 per thread)
        float acc[4][4] = {};
#pragma unroll 8
        for (int k = 0; k < DH; k++) {
            float qr[4], kr[4];
#pragma unroll
            for (int i = 0; i < 4; i++) qr[i] = Qs[(r0 + i) * SSTR + k];
#pragma unroll
            for (int j = 0; j < 4; j++) kr[j] = Ks[(c0 + j) * SSTR + k];
#pragma unroll
            for (int i = 0; i < 4; i++)
#pragma unroll
                for (int j = 0; j < 4; j++)
                    acc[i][j] += qr[i] * kr[j];
        }
#pragma unroll
        for (int i = 0; i < 4; i++)
#pragma unroll
            for (int j = 0; j < 4; j++)
                Ss[(r0 + i) * SSTR + c0 + j] = acc[i][j];
        __syncthreads();

        // online softmax: one thread per query row
        if (tid < 64) {
            float* row  = &Ss[tid * SSTR];
            float  mold = mrow[tid];
            float  mx   = mold;
            for (int c = 0; c < 64; c++) mx = fmaxf(mx, row[c]);
            float sum = 0.0f;
            for (int c = 0; c < 64; c++) {
                float p = __expf(row[c] - mx);
                row[c] = p;
                sum += p;
            }
            float fr = __expf(mold - mx);   // 0 when mold = -inf
            lrow[tid] = lrow[tid] * fr + sum;
            mrow[tid] = mx;
            frow[tid] = fr;
        }
        __syncthreads();

        // O = O * f + P @ V
#pragma unroll
        for (int i = 0; i < 4; i++) {
            const float fr = frow[r0 + i];
#pragma unroll
            for (int j = 0; j < 4; j++) o[i][j] *= fr;
        }
#pragma unroll 8
        for (int k = 0; k < 64; k++) {
            float pr[4], vr[4];
#pragma unroll
            for (int i = 0; i < 4; i++) pr[i] = Ss[(r0 + i) * SSTR + k];
#pragma unroll
            for (int j = 0; j < 4; j++) vr[j] = Vs[k * SSTR + c0 + j];
#pragma unroll
            for (int i = 0; i < 4; i++)
#pragma unroll
                for (int j = 0; j < 4; j++)
                    o[i][j] += pr[i] * vr[j];
        }
        __syncthreads();
    }

    // normalize and write ctx
#pragma unroll
    for (int i = 0; i < 4; i++) {
        const float inv = 1.0f / lrow[r0 + i];
#pragma unroll
        for (int j = 0; j < 4; j++)
            g_ctx[(long)(b * SS + q0 + r0 + i) * DD + h * DH + c0 + j] =
                o[i][j] * inv;
    }
}

// ---------------------------------------------------------------------------
// Launch
// ---------------------------------------------------------------------------
extern "C" void kernel_launch(void* const* d_in, const int* in_sizes, int n_in,
                              void* d_out, int out_size)
{
    const float* x  = (const float*)d_in[0];
    const float* Wq = (const float*)d_in[1];
    const float* bq = (const float*)d_in[2];
    const float* Wk = (const float*)d_in[3];
    const float* bk = (const float*)d_in[4];
    const float* Wv = (const float*)d_in[5];
    const float* bv = (const float*)d_in[6];
    const float* Wo = (const float*)d_in[7];
    const float* bo = (const float*)d_in[8];
    float* out = (float*)d_out;

    void *pq, *pk, *pv, *pctx;
    cudaGetSymbolAddress(&pq,   g_q);
    cudaGetSymbolAddress(&pk,   g_k);
    cudaGetSymbolAddress(&pv,   g_v);
    cudaGetSymbolAddress(&pctx, g_ctx);

    const int smem_att = (4 * 64 * SSTR + 3 * 64) * sizeof(float); // 67328 B
    cudaFuncSetAttribute(attn_kernel,
                         cudaFuncAttributeMaxDynamicSharedMemorySize, smem_att);

    dim3 ggrid(DD / 64, MM / 64);   // (12, 64)
    dim3 gthr(256);

    gemm_bias_kernel<<<ggrid, gthr>>>(x, Wq, bq, (float*)pq, MM, DD, DD);
    gemm_bias_kernel<<<ggrid, gthr>>>(x, Wk, bk, (float*)pk, MM, DD, DD);
    gemm_bias_kernel<<<ggrid, gthr>>>(x, Wv, bv, (float*)pv, MM, DD, DD);

    dim3 agrid(SS / 64, BB * HH);   // (32, 24)
    attn_kernel<<<agrid, dim3(256), smem_att>>>();

    gemm_bias_kernel<<<ggrid, gthr>>>((const float*)pctx, Wo, bo, out, MM, DD, DD);
}

// round 6
// speedup vs baseline: 1.0694x; 1.0694x over previous
#include <cuda_runtime.h>
#include <math.h>
#include <stdint.h>

#define BB 2
#define SS 2048
#define DD 768
#define HH 12
#define DH 64
#define MM (BB*SS)

// scratch (no allocations allowed — __device__ globals are the sanctioned path)
__device__ float g_q[MM*DD];
__device__ float g_k[MM*DD];
__device__ float g_v[MM*DD];
__device__ float g_ctx[MM*DD];

__device__ __forceinline__ float to_tf32(float x) {
    float y;
    asm("cvt.rna.tf32.f32 %0, %1;" : "=f"(y) : "f"(x));
    return y;
}

__device__ __forceinline__ void mma_tf32(float* d,
                                         const uint32_t* a,
                                         const uint32_t* b) {
    asm volatile(
        "mma.sync.aligned.m16n8k8.row.col.f32.tf32.tf32.f32 "
        "{%0,%1,%2,%3}, {%4,%5,%6,%7}, {%8,%9}, {%0,%1,%2,%3};"
        : "+f"(d[0]), "+f"(d[1]), "+f"(d[2]), "+f"(d[3])
        : "r"(a[0]), "r"(a[1]), "r"(a[2]), "r"(a[3]),
          "r"(b[0]), "r"(b[1]));
}

// ---------------------------------------------------------------------------
// 3xTF32 mma.sync GEMM: C[M,768] = A[M,768] @ W[768,768] + bias
// Operands split hi/lo; acc += ah*bh + ah*bl + al*bh  (near-fp32 precision).
// W used directly as col-major B ([k][n] layout == B fragment layout).
// BM=BN=128, BK=16, 256 threads (8 warps, 2x4), warp tile 64x32.
// ---------------------------------------------------------------------------
#define ASTR 20    // As row stride (16 + 4 pad, float4-aligned)
#define BSTR 132   // Bs row stride (128 + 4 pad)

__global__ void __launch_bounds__(256)
gemm_tf32_kernel(const float* __restrict__ A, const float* __restrict__ W,
                 const float* __restrict__ bias, float* __restrict__ C)
{
    __shared__ float AsH[128 * ASTR];
    __shared__ float AsL[128 * ASTR];
    __shared__ float BsH[16 * BSTR];
    __shared__ float BsL[16 * BSTR];
    __shared__ float sbias[128];

    const int tid  = threadIdx.x;
    const int warp = tid >> 5;
    const int lane = tid & 31;
    const int wm   = warp >> 2;          // 0..1 -> M offset wm*64
    const int wn   = warp & 3;           // 0..3 -> N offset wn*32
    const int m0   = blockIdx.y * 128;
    const int n0   = blockIdx.x * 128;

    if (tid < 128) sbias[tid] = bias[n0 + tid];

    // per-thread gmem load coords (2 float4 each for A and B)
    const int ar0 = tid >> 2;
    const int ak0 = (tid & 3) << 2;
    const int ar1 = (tid + 256) >> 2;
    const int ak1 = ((tid + 256) & 3) << 2;
    const int bk0 = tid >> 5;
    const int bn0q = (tid & 31) << 2;
    const int bk1 = (tid + 256) >> 5;
    const int bn1q = ((tid + 256) & 31) << 2;

    float acc[4][4][4];
#pragma unroll
    for (int i = 0; i < 4; i++)
#pragma unroll
        for (int j = 0; j < 4; j++)
#pragma unroll
            for (int q = 0; q < 4; q++) acc[i][j][q] = 0.0f;

    float4 ra0, ra1, rb0, rb1;

    ra0 = *reinterpret_cast<const float4*>(&A[(long)(m0 + ar0) * DD + ak0]);
    ra1 = *reinterpret_cast<const float4*>(&A[(long)(m0 + ar1) * DD + ak1]);
    rb0 = *reinterpret_cast<const float4*>(&W[(long)bk0 * DD + n0 + bn0q]);
    rb1 = *reinterpret_cast<const float4*>(&W[(long)bk1 * DD + n0 + bn1q]);

#define SPLIT4(v, H, L, off) do {                                            \
    float4 _h, _l;                                                           \
    _h.x = to_tf32((v).x); _l.x = to_tf32((v).x - _h.x);                     \
    _h.y = to_tf32((v).y); _l.y = to_tf32((v).y - _h.y);                     \
    _h.z = to_tf32((v).z); _l.z = to_tf32((v).z - _h.z);                     \
    _h.w = to_tf32((v).w); _l.w = to_tf32((v).w - _h.w);                     \
    *reinterpret_cast<float4*>(&(H)[off]) = _h;                              \
    *reinterpret_cast<float4*>(&(L)[off]) = _l;                              \
} while (0)

#define STORE_TILES() do {                                                   \
    SPLIT4(ra0, AsH, AsL, ar0 * ASTR + ak0);                                 \
    SPLIT4(ra1, AsH, AsL, ar1 * ASTR + ak1);                                 \
    SPLIT4(rb0, BsH, BsL, bk0 * BSTR + bn0q);                                \
    SPLIT4(rb1, BsH, BsL, bk1 * BSTR + bn1q);                                \
} while (0)

    STORE_TILES();
    __syncthreads();

    const int NITER = DD / 16;   // 48
    for (int it = 0; it < NITER; it++) {
        if (it + 1 < NITER) {
            const int k0 = (it + 1) * 16;
            ra0 = *reinterpret_cast<const float4*>(&A[(long)(m0 + ar0) * DD + k0 + ak0]);
            ra1 = *reinterpret_cast<const float4*>(&A[(long)(m0 + ar1) * DD + k0 + ak1]);
            rb0 = *reinterpret_cast<const float4*>(&W[(long)(k0 + bk0) * DD + n0 + bn0q]);
            rb1 = *reinterpret_cast<const float4*>(&W[(long)(k0 + bk1) * DD + n0 + bn1q]);
        }

#pragma unroll
        for (int ks = 0; ks < 16; ks += 8) {
            uint32_t afH[4][4], afL[4][4], bfH[4][2], bfL[4][2];
            const int kk = ks + (lane & 3);
            const int rr = (lane >> 2);
#pragma unroll
            for (int mi = 0; mi < 4; mi++) {
                const int r = wm * 64 + mi * 16 + rr;
                afH[mi][0] = __float_as_uint(AsH[r * ASTR + kk]);
                afH[mi][1] = __float_as_uint(AsH[(r + 8) * ASTR + kk]);
                afH[mi][2] = __float_as_uint(AsH[r * ASTR + kk + 4]);
                afH[mi][3] = __float_as_uint(AsH[(r + 8) * ASTR + kk + 4]);
                afL[mi][0] = __float_as_uint(AsL[r * ASTR + kk]);
                afL[mi][1] = __float_as_uint(AsL[(r + 8) * ASTR + kk]);
                afL[mi][2] = __float_as_uint(AsL[r * ASTR + kk + 4]);
                afL[mi][3] = __float_as_uint(AsL[(r + 8) * ASTR + kk + 4]);
            }
#pragma unroll
            for (int ni = 0; ni < 4; ni++) {
                const int c = wn * 32 + ni * 8 + rr;
                bfH[ni][0] = __float_as_uint(BsH[kk * BSTR + c]);
                bfH[ni][1] = __float_as_uint(BsH[(kk + 4) * BSTR + c]);
                bfL[ni][0] = __float_as_uint(BsL[kk * BSTR + c]);
                bfL[ni][1] = __float_as_uint(BsL[(kk + 4) * BSTR + c]);
            }
#pragma unroll
            for (int mi = 0; mi < 4; mi++)
#pragma unroll
                for (int ni = 0; ni < 4; ni++) {
                    mma_tf32(acc[mi][ni], afH[mi], bfL[ni]);
                    mma_tf32(acc[mi][ni], afL[mi], bfH[ni]);
                    mma_tf32(acc[mi][ni], afH[mi], bfH[ni]);
                }
        }
        __syncthreads();
        if (it + 1 < NITER) {
            STORE_TILES();
            __syncthreads();
        }
    }

    // epilogue: bias + store
    const int rr = lane >> 2;
    const int cc = (lane & 3) * 2;
#pragma unroll
    for (int mi = 0; mi < 4; mi++) {
#pragma unroll
        for (int ni = 0; ni < 4; ni++) {
            const int col = wn * 32 + ni * 8 + cc;
            const int row = m0 + wm * 64 + mi * 16 + rr;
            float2 o0, o1;
            o0.x = acc[mi][ni][0] + sbias[col];
            o0.y = acc[mi][ni][1] + sbias[col + 1];
            o1.x = acc[mi][ni][2] + sbias[col];
            o1.y = acc[mi][ni][3] + sbias[col + 1];
            *reinterpret_cast<float2*>(&C[(long)row * DD + n0 + col]) = o0;
            *reinterpret_cast<float2*>(&C[(long)(row + 8) * DD + n0 + col]) = o1;
        }
    }
}

// ---------------------------------------------------------------------------
// Flash attention (fp32) with parallel softmax
// ---------------------------------------------------------------------------
#define SSTR 65

__global__ void attn_kernel()
{
    extern __shared__ float sm_att[];
    const int bh = blockIdx.y;
    const int b  = bh / HH;
    const int h  = bh % HH;
    const int q0 = blockIdx.x * 64;

    float* Qs   = sm_att;
    float* Ks   = Qs + 64 * SSTR;
    float* Vs   = Ks + 64 * SSTR;
    float* Ss   = Vs + 64 * SSTR;
    float* mrow = Ss + 64 * SSTR;
    float* lrow = mrow + 64;
    float* frow = lrow + 64;

    const int tid = threadIdx.x;
    const int r0  = (tid >> 4) * 4;
    const int c0  = (tid & 15) * 4;
    const bool rowlead = ((tid & 15) == 0);

    for (int idx = tid; idx < 64 * 64; idx += 256) {
        const int r = idx >> 6, c = idx & 63;
        Qs[r * SSTR + c] = g_q[(long)(b * SS + q0 + r) * DD + h * DH + c];
    }
    if (tid < 64) { mrow[tid] = -INFINITY; lrow[tid] = 0.0f; }

    float o[4][4] = {};
    __syncthreads();

    for (int kt = 0; kt < SS / 64; kt++) {
        const int k0 = kt * 64;
        for (int idx = tid; idx < 64 * 64; idx += 256) {
            const int r = idx >> 6, c = idx & 63;
            const long g = (long)(b * SS + k0 + r) * DD + h * DH + c;
            Ks[r * SSTR + c] = g_k[g];
            Vs[r * SSTR + c] = g_v[g];
        }
        __syncthreads();

        float acc[4][4] = {};
#pragma unroll 8
        for (int k = 0; k < DH; k++) {
            float qr[4], kr[4];
#pragma unroll
            for (int i = 0; i < 4; i++) qr[i] = Qs[(r0 + i) * SSTR + k];
#pragma unroll
            for (int j = 0; j < 4; j++) kr[j] = Ks[(c0 + j) * SSTR + k];
#pragma unroll
            for (int i = 0; i < 4; i++)
#pragma unroll
                for (int j = 0; j < 4; j++)
                    acc[i][j] += qr[i] * kr[j];
        }

        // parallel online softmax: 16 threads per row cooperate
#pragma unroll
        for (int i = 0; i < 4; i++) {
            const int r = r0 + i;
            float mi = fmaxf(fmaxf(acc[i][0], acc[i][1]),
                             fmaxf(acc[i][2], acc[i][3]));
#pragma unroll
            for (int off = 1; off < 16; off <<= 1)
                mi = fmaxf(mi, __shfl_xor_sync(0xffffffffu, mi, off));
            const float mold = mrow[r];
            const float mx   = fmaxf(mold, mi);
            float s = 0.0f;
#pragma unroll
            for (int j = 0; j < 4; j++) {
                const float p = __expf(acc[i][j] - mx);
                Ss[r * SSTR + c0 + j] = p;
                s += p;
            }
#pragma unroll
            for (int off = 1; off < 16; off <<= 1)
                s += __shfl_xor_sync(0xffffffffu, s, off);
            if (rowlead) {
                const float fr = __expf(mold - mx);
                frow[r] = fr;
                lrow[r] = lrow[r] * fr + s;
                mrow[r] = mx;
            }
        }
        __syncthreads();

#pragma unroll
        for (int i = 0; i < 4; i++) {
            const float fr = frow[r0 + i];
#pragma unroll
            for (int j = 0; j < 4; j++) o[i][j] *= fr;
        }
#pragma unroll 8
        for (int k = 0; k < 64; k++) {
            float pr[4], vr[4];
#pragma unroll
            for (int i = 0; i < 4; i++) pr[i] = Ss[(r0 + i) * SSTR + k];
#pragma unroll
            for (int j = 0; j < 4; j++) vr[j] = Vs[k * SSTR + c0 + j];
#pragma unroll
            for (int i = 0; i < 4; i++)
#pragma unroll
                for (int j = 0; j < 4; j++)
                    o[i][j] += pr[i] * vr[j];
        }
        __syncthreads();
    }

#pragma unroll
    for (int i = 0; i < 4; i++) {
        const float inv = 1.0f / lrow[r0 + i];
#pragma unroll
        for (int j = 0; j < 4; j++)
            g_ctx[(long)(b * SS + q0 + r0 + i) * DD + h * DH + c0 + j] =
                o[i][j] * inv;
    }
}

// ---------------------------------------------------------------------------
// Launch
// ---------------------------------------------------------------------------
extern "C" void kernel_launch(void* const* d_in, const int* in_sizes, int n_in,
                              void* d_out, int out_size)
{
    const float* x  = (const float*)d_in[0];
    const float* Wq = (const float*)d_in[1];
    const float* bq = (const float*)d_in[2];
    const float* Wk = (const float*)d_in[3];
    const float* bk = (const float*)d_in[4];
    const float* Wv = (const float*)d_in[5];
    const float* bv = (const float*)d_in[6];
    const float* Wo = (const float*)d_in[7];
    const float* bo = (const float*)d_in[8];
    float* out = (float*)d_out;

    void *pq, *pk, *pv, *pctx;
    cudaGetSymbolAddress(&pq,   g_q);
    cudaGetSymbolAddress(&pk,   g_k);
    cudaGetSymbolAddress(&pv,   g_v);
    cudaGetSymbolAddress(&pctx, g_ctx);

    const int smem_att = (4 * 64 * SSTR + 3 * 64) * sizeof(float);
    cudaFuncSetAttribute(attn_kernel,
                         cudaFuncAttributeMaxDynamicSharedMemorySize, smem_att);

    dim3 ggrid(DD / 128, MM / 128);   // (6, 32)

    gemm_tf32_kernel<<<ggrid, 256>>>(x, Wq, bq, (float*)pq);
    gemm_tf32_kernel<<<ggrid, 256>>>(x, Wk, bk, (float*)pk);
    gemm_tf32_kernel<<<ggrid, 256>>>(x, Wv, bv, (float*)pv);

    dim3 agrid(SS / 64, BB * HH);     // (32, 24)
    attn_kernel<<<agrid, dim3(256), smem_att>>>();

    gemm_tf32_kernel<<<ggrid, 256>>>((const float*)pctx, Wo, bo, out);
}